// round 9
// baseline (speedup 1.0000x reference)
#include <cuda_runtime.h>
#include <math.h>

// ---------------------------------------------------------------------------
// NISQ classifier via Pauli-transfer-matrix simulation — ONE persistent kernel.
// State c[p], p = 10 base-4 digits (slots). Qubit -> slot:
//   q:    0  1  2  3  4  5  6  7  8  9
//   slot: 0  2  3  4  5  1  6  7  8  9
// Stage A (KIND 0): slots 0-5 (bits 0-11)            -> CNOT 01,12,23,34,45
// Stage B (KIND 1): slots {0,1,6..9} (bits 0-3,12-19)-> CNOT 56,67,78,89,90
// 3 layers x (A,B) separated by software grid barriers; logits fused at end.
// NBLK=128 <= #SMs -> all blocks co-resident at any achievable occupancy.
// Barrier spins are BOUNDED: a broken barrier ends the kernel (wrong output,
// loud bench failure) instead of hanging the container.
// ---------------------------------------------------------------------------

#define NSTATE (1 << 20)
#define NBLK 128u

__device__ float    g_c[NSTATE];      // PTM state vector (4 MB)
__device__ unsigned g_count = 0;      // barrier arrivals (self-resetting)
__device__ unsigned g_sense = 0;      // barrier sense (6 flips/run -> back to 0)

// Bank swizzle: phys = u ^ SWf(u); linear over u bits 5-8 -> bank bits 0-4.
// Conflict-free for every pass pattern below (R4-verified, measured good).
__device__ __host__ constexpr unsigned SWf(unsigned u) {
    return ((((u >> 5) ^ (u >> 7)) & 1u))
         | ((((u >> 6)) & 1u) << 1)
         | ((((u >> 5) ^ (u >> 6)) & 1u) << 2)
         | ((((u >> 6) ^ (u >> 7)) & 1u) << 3)
         | ((((u >> 8)) & 1u) << 4);
}

// Software grid barrier (sense-reversing). Bounded spin: never hangs.
__device__ __forceinline__ void grid_barrier(unsigned* sense) {
    __threadfence();
    __syncthreads();
    unsigned want = *sense ^ 1u;
    *sense = want;
    if (threadIdx.x == 0) {
        unsigned old = atomicAdd(&g_count, 1u);
        if (old == NBLK - 1u) {
            g_count = 0u;            // all arrived; next inc only after release
            __threadfence();
            atomicExch(&g_sense, want);
        } else {
            unsigned spins = 0;
            while (*(volatile unsigned*)&g_sense != want) {
                __nanosleep(64);
                if (++spins > (1u << 22)) break;   // escape hatch (~0.2s)
            }
        }
        __threadfence();
    }
    __syncthreads();
}

// Build fused single-qubit PTM op: M = phase*amp*depol1*Rot (4x4, row I = e0)
__device__ __forceinline__ void build_M(float phi, float th, float om, float* M) {
    float cphi = cosf(phi), sphi = sinf(phi);
    float cth  = cosf(th),  sth  = sinf(th);
    float com  = cosf(om),  som  = sinf(om);
    float A[9]  = {com, -som, 0.f,  som, com, 0.f,  0.f, 0.f, 1.f};
    float Bm[9] = {cth, 0.f, sth,   0.f, 1.f, 0.f,  -sth, 0.f, cth};
    float C[9]  = {cphi, -sphi, 0.f, sphi, cphi, 0.f, 0.f, 0.f, 1.f};
    float AB[9], R[9];
#pragma unroll
    for (int i = 0; i < 3; i++)
#pragma unroll
        for (int j = 0; j < 3; j++) {
            float s = 0.f;
#pragma unroll
            for (int k = 0; k < 3; k++) s += A[i*3+k] * Bm[k*3+j];
            AB[i*3+j] = s;
        }
#pragma unroll
    for (int i = 0; i < 3; i++)
#pragma unroll
        for (int j = 0; j < 3; j++) {
            float s = 0.f;
#pragma unroll
            for (int k = 0; k < 3; k++) s += AB[i*3+k] * C[k*3+j];
            R[i*3+j] = s;
        }
    const float gamma = -expm1f(-1e-7f / 0.05f);
    const float gph   = -expm1f(-1e-7f / 0.07f);
    const float c1    = 1.0f - 4.0f * 0.001f / 3.0f;
    float sq = sqrtf((1.f - gamma) * (1.f - gph));
    float a1 = sq * c1, z1 = (1.f - gamma) * c1, g1 = gamma;
    M[0]  = 1.f; M[1]  = 0.f;       M[2]  = 0.f;       M[3]  = 0.f;
    M[4]  = 0.f; M[5]  = a1 * R[0]; M[6]  = a1 * R[1]; M[7]  = a1 * R[2];
    M[8]  = 0.f; M[9]  = a1 * R[3]; M[10] = a1 * R[4]; M[11] = a1 * R[5];
    M[12] = g1;  M[13] = z1 * R[6]; M[14] = z1 * R[7]; M[15] = z1 * R[8];
}

// Fused pass (R4, byte-identical numerics): optional single ops, CNOT signed
// permutation, per-wire 2-qubit noise. One 16-elem group per thread.
template<int PC, int PT, bool HASMT, bool HASMC>
__device__ __forceinline__ void pass(float* t,
                                     const float* __restrict__ MT,
                                     const float* __restrict__ MC,
                                     float aN, float zN, float gN) {
    constexpr int sc = 2 * PC, st = 2 * PT;
    constexpr int plo  = (sc < st) ? sc : st;
    constexpr int phi_ = (sc < st) ? st : sc;
    constexpr int midw = phi_ - plo - 2;
    unsigned g    = threadIdx.x;
    unsigned lo   = g & ((1u << plo) - 1u);
    unsigned rest = g >> plo;
    unsigned mid  = rest & ((1u << midw) - 1u);
    unsigned hi   = rest >> midw;
    unsigned base = lo | (mid << (plo + 2)) | (hi << (phi_ + 2));
    unsigned pb   = base ^ SWf(base);

    float v[16];
#pragma unroll
    for (int dc = 0; dc < 4; dc++)
#pragma unroll
        for (int dt = 0; dt < 4; dt++) {
            unsigned off = ((unsigned)dc << sc) | ((unsigned)dt << st);
            v[dc * 4 + dt] = t[pb ^ off ^ SWf(off)];
        }

    if (HASMT) {
#pragma unroll
        for (int dc = 0; dc < 4; dc++) {
            float v0 = v[dc*4+0], v1 = v[dc*4+1], v2 = v[dc*4+2], v3 = v[dc*4+3];
            v[dc*4+1] = MT[5]  * v1 + MT[6]  * v2 + MT[7]  * v3;
            v[dc*4+2] = MT[9]  * v1 + MT[10] * v2 + MT[11] * v3;
            v[dc*4+3] = MT[12] * v0 + MT[13] * v1 + MT[14] * v2 + MT[15] * v3;
        }
    }
    if (HASMC) {
#pragma unroll
        for (int dt = 0; dt < 4; dt++) {
            float v0 = v[0+dt], v1 = v[4+dt], v2 = v[8+dt], v3 = v[12+dt];
            v[4 + dt]  = MC[5]  * v1 + MC[6]  * v2 + MC[7]  * v3;
            v[8 + dt]  = MC[9]  * v1 + MC[10] * v2 + MC[11] * v3;
            v[12 + dt] = MC[12] * v0 + MC[13] * v1 + MC[14] * v2 + MC[15] * v3;
        }
    }

    const int tbl[16] = {0, 1, 14, 15, 5, 4, 11, 10, 9, 8, 7, 6, 12, 13, 2, 3};
    float w_[16];
#pragma unroll
    for (int i = 0; i < 16; i++) w_[i] = v[tbl[i]];
    w_[7]  = -w_[7];
    w_[10] = -w_[10];
#pragma unroll
    for (int dt = 0; dt < 4; dt++) {
        float u0 = w_[0+dt], u1 = w_[4+dt], u2 = w_[8+dt], u3 = w_[12+dt];
        w_[4 + dt]  = aN * u1;
        w_[8 + dt]  = aN * u2;
        w_[12 + dt] = gN * u0 + zN * u3;
    }
#pragma unroll
    for (int dc = 0; dc < 4; dc++) {
        float u0 = w_[dc*4+0], u1 = w_[dc*4+1], u2 = w_[dc*4+2], u3 = w_[dc*4+3];
        w_[dc*4+1] = aN * u1;
        w_[dc*4+2] = aN * u2;
        w_[dc*4+3] = gN * u0 + zN * u3;
    }
#pragma unroll
    for (int dc = 0; dc < 4; dc++)
#pragma unroll
        for (int dt = 0; dt < 4; dt++) {
            unsigned off = ((unsigned)dc << sc) | ((unsigned)dt << st);
            t[pb ^ off ^ SWf(off)] = w_[dc * 4 + dt];
        }
}

template<int KIND>
__device__ __forceinline__ unsigned gidx(unsigned u, unsigned tile) {
    if (KIND == 0) return u | (tile << 12);
    else           return (u & 15u) | (tile << 4) | ((u >> 4) << 12);
}

// One 4096-elem tile through a stage (R4 sim_kernel body as device function).
template<int KIND, bool INIT>
__device__ __forceinline__ void do_tile(float* t, const float sM[10][16],
                                        unsigned tile, unsigned tid,
                                        float aN, float zN, float gN) {
    if (INIT) {
        for (unsigned u = tid; u < 4096; u += 256) {
            unsigned p = gidx<KIND>(u, tile);
            t[u ^ SWf(u)] = ((((p >> 1) ^ p) & 0x55555u) == 0u) ? 1.0f : 0.0f;
        }
    } else {
#pragma unroll
        for (int i = 0; i < 4; i++) {
            unsigned u = (tid + i * 256u) * 4u;
            float4 r = *(const float4*)&g_c[gidx<KIND>(u, tile)];
            unsigned sw = SWf(u);
            t[(u + 0) ^ sw] = r.x;
            t[(u + 1) ^ sw] = r.y;
            t[(u + 2) ^ sw] = r.z;
            t[(u + 3) ^ sw] = r.w;
        }
    }
    __syncthreads();

    if (KIND == 0) {
        pass<0, 2, true, true >(t, sM[1], sM[0], aN, zN, gN); __syncthreads();
        pass<2, 3, true, false>(t, sM[2], 0,     aN, zN, gN); __syncthreads();
        pass<3, 4, true, false>(t, sM[3], 0,     aN, zN, gN); __syncthreads();
        pass<4, 5, true, false>(t, sM[4], 0,     aN, zN, gN); __syncthreads();
        pass<5, 1, true, false>(t, sM[5], 0,     aN, zN, gN); __syncthreads();
    } else {
        pass<1, 2, true, false>(t, sM[6], 0, aN, zN, gN); __syncthreads();
        pass<2, 3, true, false>(t, sM[7], 0, aN, zN, gN); __syncthreads();
        pass<3, 4, true, false>(t, sM[8], 0, aN, zN, gN); __syncthreads();
        pass<4, 5, true, false>(t, sM[9], 0, aN, zN, gN); __syncthreads();
        pass<5, 0, false,false>(t, 0,     0, aN, zN, gN); __syncthreads();
    }

#pragma unroll
    for (int i = 0; i < 4; i++) {
        unsigned u = (tid + i * 256u) * 4u;
        unsigned sw = SWf(u);
        float4 r;
        r.x = t[(u + 0) ^ sw];
        r.y = t[(u + 1) ^ sw];
        r.z = t[(u + 2) ^ sw];
        r.w = t[(u + 3) ^ sw];
        *(float4*)&g_c[gidx<KIND>(u, tile)] = r;
    }
    __syncthreads();
}

// ---------------------------------------------------------------------------
// Whole pipeline in ONE kernel: 128 blocks x 256 threads (always co-resident).
// Each block: 2 tiles per stage; 16 logits rows at the end.
// ---------------------------------------------------------------------------
__global__ void __launch_bounds__(256, 2)
mega_kernel(const float* __restrict__ wts, const float* __restrict__ x,
            const float* __restrict__ bvec, const float* __restrict__ w,
            float* __restrict__ out) {
    __shared__ float t[4096];
    __shared__ float sM[10][16];
    __shared__ float cA[10], cB[10];
    __shared__ float red[8];
    unsigned blk = blockIdx.x, tid = threadIdx.x;
    unsigned sense = 0;

    const float gamma = -expm1f(-1e-7f / 0.05f);
    const float gph   = -expm1f(-1e-7f / 0.07f);
    const float c2    = 1.0f - 4.0f * 0.01f / 3.0f;
    const float aN = sqrtf((1.f - gamma) * (1.f - gph)) * c2;
    const float zN = (1.f - gamma) * c2;
    const float gN = gamma;

    // ---- simulation: 3 layers x (stage A, stage B), 6 grid barriers ----
#pragma unroll 1
    for (int l = 0; l < 3; l++) {
        if (tid < 10) {
            const float* a = wts + (l * 10 + (int)tid) * 3;
            build_M(a[0], a[1], a[2], sM[tid]);
        }
        __syncthreads();
        if (l == 0) {
            do_tile<0, true >(t, sM, blk,        tid, aN, zN, gN);
            do_tile<0, true >(t, sM, blk + NBLK, tid, aN, zN, gN);
        } else {
            do_tile<0, false>(t, sM, blk,        tid, aN, zN, gN);
            do_tile<0, false>(t, sM, blk + NBLK, tid, aN, zN, gN);
        }
        grid_barrier(&sense);
        do_tile<1, false>(t, sM, blk,        tid, aN, zN, gN);
        do_tile<1, false>(t, sM, blk + NBLK, tid, aN, zN, gN);
        grid_barrier(&sense);
    }
    // sense flipped 6 times -> g_sense/g_count back to 0: replay-deterministic.

    // ---- logits: 16 rows per block, next-row prefetch ----
    if (tid < 10) {
        const int slot_of_q[10] = {0, 2, 3, 4, 5, 1, 6, 7, 8, 9};
        int q = (int)tid;
        int j = 9 - q;
        int s2 = 2 * slot_of_q[q];
        cA[j] = w[2 * q] * g_c[1u << s2];
        cB[j] = w[2 * q + 1] * 0.96f * g_c[3u << s2];   // readout: 1-2*0.02
    }
    float4 bv = ((const float4*)bvec)[tid];
    float4 xv = ((const float4*)(x + ((int)blk * 16) * 1024))[tid];
    __syncthreads();

#pragma unroll 1
    for (int r = 0; r < 16; r++) {
        int row = (int)blk * 16 + r;
        t[tid * 4 + 0] = xv.x + bv.x;
        t[tid * 4 + 1] = xv.y + bv.y;
        t[tid * 4 + 2] = xv.z + bv.z;
        t[tid * 4 + 3] = xv.w + bv.w;
        __syncthreads();
        if (r < 15)   // prefetch next row while computing this one
            xv = ((const float4*)(x + (row + 1) * 1024))[tid];

        float acc = 0.f;
        for (int m = (int)tid; m < 1024; m += 256) {
            float xm = t[m];
            float s = 0.f;
#pragma unroll
            for (int j = 0; j < 10; j++) {
                s += cA[j] * t[m ^ (1 << j)];
                s += cB[j] * (((m >> j) & 1) ? -xm : xm);
            }
            acc += xm * s;
        }
#pragma unroll
        for (int off = 16; off > 0; off >>= 1)
            acc += __shfl_down_sync(0xFFFFFFFFu, acc, off);
        if ((tid & 31) == 0) red[tid >> 5] = acc;
        __syncthreads();
        if (tid == 0) {
            float a = red[0] + red[1] + red[2] + red[3]
                    + red[4] + red[5] + red[6] + red[7];
            out[row] = 1.f / (1.f + expf(-a));
        }
        __syncthreads();
    }
}

// ---------------------------------------------------------------------------
extern "C" void kernel_launch(void* const* d_in, const int* in_sizes, int n_in,
                              void* d_out, int out_size) {
    const float* x = nullptr;
    const float* bv = nullptr;
    const float* w = nullptr;
    const float* cw = nullptr;
    for (int i = 0; i < n_in; i++) {
        switch (in_sizes[i]) {
            case 2048 * 1024: x = (const float*)d_in[i]; break;
            case 1024:        bv = (const float*)d_in[i]; break;
            case 20:          w = (const float*)d_in[i]; break;
            case 90:          cw = (const float*)d_in[i]; break;
            default: break;  // P_tensor unused
        }
    }
    mega_kernel<<<NBLK, 256>>>(cw, x, bv, w, (float*)d_out);
}

// round 10
// speedup vs baseline: 1.2172x; 1.2172x over previous
#include <cuda_runtime.h>
#include <math.h>

// ---------------------------------------------------------------------------
// NISQ classifier via Pauli-transfer-matrix simulation.
// State c[p], p = 10 base-4 digits (slots). Qubit -> slot:
//   q:    0  1  2  3  4  5  6  7  8  9
//   slot: 0  2  3  4  5  1  6  7  8  9
// Stage A (KIND 0): slots 0-5 (bits 0-11)            -> CNOT 01,12,23,34,45
// Stage B (KIND 1): slots {0,1,6..9} (bits 0-3,12-19)-> CNOT 56,67,78,89,90
// Half-group ownership: the CNOT PTM permutation + noise closes over row-sets
// {0,3} and {1,2} of the control digit, so each 16-elem group splits into two
// independent 8-elem halves -> 512 threads/block, no shuffles.
// ---------------------------------------------------------------------------

#define NSTATE (1 << 20)
__device__ float g_c[NSTATE];   // PTM state vector (4 MB)

// Bank swizzle: phys = u ^ SWf(u); linear over u bits 5-8 -> bank bits 0-4.
// Each warp spans 32 consecutive groups with fixed (row,dt) offset, identical
// to the R4 access pattern -> conflict-freedom carries over.
__device__ __host__ constexpr unsigned SWf(unsigned u) {
    return ((((u >> 5) ^ (u >> 7)) & 1u))
         | ((((u >> 6)) & 1u) << 1)
         | ((((u >> 5) ^ (u >> 6)) & 1u) << 2)
         | ((((u >> 6) ^ (u >> 7)) & 1u) << 3)
         | ((((u >> 8)) & 1u) << 4);
}

// Build fused single-qubit PTM op: M = phase*amp*depol1*Rot (4x4, row I = e0)
__device__ __forceinline__ void build_M(float phi, float th, float om, float* M) {
    float cphi = cosf(phi), sphi = sinf(phi);
    float cth  = cosf(th),  sth  = sinf(th);
    float com  = cosf(om),  som  = sinf(om);
    float A[9]  = {com, -som, 0.f,  som, com, 0.f,  0.f, 0.f, 1.f};
    float Bm[9] = {cth, 0.f, sth,   0.f, 1.f, 0.f,  -sth, 0.f, cth};
    float C[9]  = {cphi, -sphi, 0.f, sphi, cphi, 0.f, 0.f, 0.f, 1.f};
    float AB[9], R[9];
#pragma unroll
    for (int i = 0; i < 3; i++)
#pragma unroll
        for (int j = 0; j < 3; j++) {
            float s = 0.f;
#pragma unroll
            for (int k = 0; k < 3; k++) s += A[i*3+k] * Bm[k*3+j];
            AB[i*3+j] = s;
        }
#pragma unroll
    for (int i = 0; i < 3; i++)
#pragma unroll
        for (int j = 0; j < 3; j++) {
            float s = 0.f;
#pragma unroll
            for (int k = 0; k < 3; k++) s += AB[i*3+k] * C[k*3+j];
            R[i*3+j] = s;
        }
    const float gamma = -expm1f(-1e-7f / 0.05f);
    const float gph   = -expm1f(-1e-7f / 0.07f);
    const float c1    = 1.0f - 4.0f * 0.001f / 3.0f;
    float sq = sqrtf((1.f - gamma) * (1.f - gph));
    float a1 = sq * c1, z1 = (1.f - gamma) * c1, g1 = gamma;
    M[0]  = 1.f; M[1]  = 0.f;       M[2]  = 0.f;       M[3]  = 0.f;
    M[4]  = 0.f; M[5]  = a1 * R[0]; M[6]  = a1 * R[1]; M[7]  = a1 * R[2];
    M[8]  = 0.f; M[9]  = a1 * R[3]; M[10] = a1 * R[4]; M[11] = a1 * R[5];
    M[12] = g1;  M[13] = z1 * R[6]; M[14] = z1 * R[7]; M[15] = z1 * R[8];
}

// Half-group pass: thread owns rows {0,3} (h=0) or {1,2} (h=1) of one group.
// Numerics identical to R4's pass (perm -> control noise -> target noise).
template<int PC, int PT, bool HASMT>
__device__ __forceinline__ void hpass(float* __restrict__ t,
                                      const float* __restrict__ MT,
                                      float aN, float zN, float gN) {
    constexpr int sc = 2 * PC, st = 2 * PT;
    constexpr int plo  = (sc < st) ? sc : st;
    constexpr int phi_ = (sc < st) ? st : sc;
    constexpr int midw = phi_ - plo - 2;
    constexpr unsigned C1 = (1u << st) ^ SWf(1u << st);
    constexpr unsigned C2 = (2u << st) ^ SWf(2u << st);
    constexpr unsigned C3 = (3u << st) ^ SWf(3u << st);

    unsigned tid = threadIdx.x;
    unsigned g   = tid & 255u;         // group id (256 groups/tile)
    unsigned h   = tid >> 8;           // 0: rows {0,3}; 1: rows {1,2} (warp-uniform)
    unsigned rA  = h;                  // 0 / 1
    unsigned rB  = 3u - h;             // 3 / 2

    unsigned lo   = g & ((1u << plo) - 1u);
    unsigned rest = g >> plo;
    unsigned mid  = rest & ((1u << midw) - 1u);
    unsigned hi   = rest >> midw;
    unsigned base = lo | (mid << (plo + 2)) | (hi << (phi_ + 2));
    unsigned bA = base | (rA << sc);
    unsigned bB = base | (rB << sc);
    unsigned pA = bA ^ SWf(bA);
    unsigned pB = bB ^ SWf(bB);

    float a0 = t[pA], a1 = t[pA ^ C1], a2 = t[pA ^ C2], a3 = t[pA ^ C3];
    float b0 = t[pB], b1 = t[pB ^ C1], b2 = t[pB ^ C2], b3 = t[pB ^ C3];

    if (HASMT) {   // single-qubit op on target digit (within-row)
        float x1 = MT[5]*a1 + MT[6]*a2 + MT[7]*a3;
        float x2 = MT[9]*a1 + MT[10]*a2 + MT[11]*a3;
        float x3 = MT[12]*a0 + MT[13]*a1 + MT[14]*a2 + MT[15]*a3;
        a1 = x1; a2 = x2; a3 = x3;
        float y1 = MT[5]*b1 + MT[6]*b2 + MT[7]*b3;
        float y2 = MT[9]*b1 + MT[10]*b2 + MT[11]*b3;
        float y3 = MT[12]*b0 + MT[13]*b1 + MT[14]*b2 + MT[15]*b3;
        b1 = y1; b2 = y2; b3 = y3;
    }

    float A0, A1, A2, A3, B0, B1, B2, B3;
    if (h == 0) {
        // perm: out0 = {in0_0, in0_1, in3_2, in3_3}; out3 = {in3_0, in3_1, in0_2, in0_3}
        A0 = a0; A1 = a1; A2 = b2; A3 = b3;
        B0 = b0; B1 = b1; B2 = a2; B3 = a3;
        // control noise: row0 unchanged; row3 <- gN*row0 + zN*row3
        float n0 = gN * A0 + zN * B0;
        float n1 = gN * A1 + zN * B1;
        float n2 = gN * A2 + zN * B2;
        float n3 = gN * A3 + zN * B3;
        B0 = n0; B1 = n1; B2 = n2; B3 = n3;
    } else {
        // perm: out1 = {in1_1, in1_0, in2_3, -in2_2}; out2 = {in2_1, in2_0, -in1_3, in1_2}
        A0 = aN * a1; A1 = aN * a0; A2 = aN * b3; A3 = -aN * b2;
        B0 = aN * b1; B1 = aN * b0; B2 = -aN * a3; B3 = aN * b2 * 0.f + aN * a2;  // aN*in1_2
    }
    // target noise per row: {v0, aN v1, aN v2, gN v0 + zN v3}
    float oA3 = gN * A0 + zN * A3;
    float oB3 = gN * B0 + zN * B3;
    t[pA]      = A0;
    t[pA ^ C1] = aN * A1;
    t[pA ^ C2] = aN * A2;
    t[pA ^ C3] = oA3;
    t[pB]      = B0;
    t[pB ^ C1] = aN * B1;
    t[pB ^ C2] = aN * B2;
    t[pB ^ C3] = oB3;
}

template<int KIND>
__device__ __forceinline__ unsigned gidx(unsigned u, unsigned tile) {
    if (KIND == 0) return u | (tile << 12);
    else           return (u & 15u) | (tile << 4) | ((u >> 4) << 12);
}

// ---------------------------------------------------------------------------
// Sim kernel: 256 blocks x 512 threads, 4096-float swizzled smem tile.
// Stage A folds M0 into the boundary load (digit 0 = one aligned float4).
// ---------------------------------------------------------------------------
template<int KIND, bool INIT>
__global__ __launch_bounds__(512) void sim_kernel(const float* __restrict__ wts,
                                                  int layer) {
    __shared__ float t[4096];
    __shared__ float sM[10][16];
    unsigned blk = blockIdx.x, tid = threadIdx.x;

    // Issue global loads first so they overlap with build_M trig.
    float4 r[2];
#pragma unroll
    for (int i = 0; i < 2; i++) {
        unsigned u = (tid + i * 512u) * 4u;
        if (INIT) {
            unsigned p = gidx<KIND>(u, blk);
            float v = ((((p >> 1) ^ p) & 0x55555u) == 0u) ? 1.0f : 0.0f;
            r[i].x = v; r[i].y = 0.f; r[i].z = 0.f; r[i].w = v;
        } else {
            r[i] = *(const float4*)&g_c[gidx<KIND>(u, blk)];
        }
    }
    if (tid < 10) {
        const float* a = wts + (layer * 10 + (int)tid) * 3;
        build_M(a[0], a[1], a[2], sM[tid]);
    }
    __syncthreads();

#pragma unroll
    for (int i = 0; i < 2; i++) {
        unsigned u = (tid + i * 512u) * 4u;
        float4 v = r[i];
        if (KIND == 0) {   // fold M0 (slot 0 = bits 0-1 of tile index)
            float x1 = sM[0][5]*v.y + sM[0][6]*v.z + sM[0][7]*v.w;
            float x2 = sM[0][9]*v.y + sM[0][10]*v.z + sM[0][11]*v.w;
            float x3 = sM[0][12]*v.x + sM[0][13]*v.y + sM[0][14]*v.z + sM[0][15]*v.w;
            v.y = x1; v.z = x2; v.w = x3;
        }
        unsigned sw = SWf(u);
        t[(u + 0) ^ sw] = v.x;
        t[(u + 1) ^ sw] = v.y;
        t[(u + 2) ^ sw] = v.z;
        t[(u + 3) ^ sw] = v.w;
    }
    __syncthreads();

    const float gamma = -expm1f(-1e-7f / 0.05f);
    const float gph   = -expm1f(-1e-7f / 0.07f);
    const float c2    = 1.0f - 4.0f * 0.01f / 3.0f;
    const float aN = sqrtf((1.f - gamma) * (1.f - gph)) * c2;
    const float zN = (1.f - gamma) * c2;
    const float gN = gamma;

    if (KIND == 0) {
        // local pos: q0->0 q5->1 q1->2 q2->3 q3->4 q4->5
        hpass<0, 2, true>(t, sM[1], aN, zN, gN); __syncthreads(); // M1, CNOT(q0,q1)
        hpass<2, 3, true>(t, sM[2], aN, zN, gN); __syncthreads(); // M2, CNOT(q1,q2)
        hpass<3, 4, true>(t, sM[3], aN, zN, gN); __syncthreads(); // M3, CNOT(q2,q3)
        hpass<4, 5, true>(t, sM[4], aN, zN, gN); __syncthreads(); // M4, CNOT(q3,q4)
        hpass<5, 1, true>(t, sM[5], aN, zN, gN); __syncthreads(); // M5, CNOT(q4,q5)
    } else {
        // local pos: q0->0 q5->1 q6->2 q7->3 q8->4 q9->5
        hpass<1, 2, true >(t, sM[6], aN, zN, gN); __syncthreads(); // M6, CNOT(q5,q6)
        hpass<2, 3, true >(t, sM[7], aN, zN, gN); __syncthreads(); // M7, CNOT(q6,q7)
        hpass<3, 4, true >(t, sM[8], aN, zN, gN); __syncthreads(); // M8, CNOT(q7,q8)
        hpass<4, 5, true >(t, sM[9], aN, zN, gN); __syncthreads(); // M9, CNOT(q8,q9)
        hpass<5, 0, false>(t, 0,     aN, zN, gN); __syncthreads(); // CNOT(q9,q0)
    }

#pragma unroll
    for (int i = 0; i < 2; i++) {
        unsigned u = (tid + i * 512u) * 4u;
        unsigned sw = SWf(u);
        float4 v;
        v.x = t[(u + 0) ^ sw];
        v.y = t[(u + 1) ^ sw];
        v.z = t[(u + 2) ^ sw];
        v.w = t[(u + 3) ^ sw];
        *(float4*)&g_c[gidx<KIND>(u, blk)] = v;
    }
}

// ---------------------------------------------------------------------------
// Logits: one block per batch row.
// ---------------------------------------------------------------------------
__global__ __launch_bounds__(256) void logits_kernel(
    const float* __restrict__ x, const float* __restrict__ bvec,
    const float* __restrict__ w, float* __restrict__ out) {
    __shared__ float xs[1024];
    __shared__ float cA[10], cB[10];
    __shared__ float red[8];
    int row = blockIdx.x, tid = threadIdx.x;

    for (int m = tid; m < 1024; m += 256)
        xs[m] = x[row * 1024 + m] + bvec[m];

    if (tid < 10) {
        const int slot_of_q[10] = {0, 2, 3, 4, 5, 1, 6, 7, 8, 9};
        int q = tid;
        int j = 9 - q;
        int s2 = 2 * slot_of_q[q];
        cA[j] = w[2 * q] * g_c[1u << s2];
        cB[j] = w[2 * q + 1] * 0.96f * g_c[3u << s2];   // readout: 1-2*0.02
    }
    __syncthreads();

    float acc = 0.f;
    for (int m = tid; m < 1024; m += 256) {
        float xm = xs[m];
        float s = 0.f;
#pragma unroll
        for (int j = 0; j < 10; j++) {
            s += cA[j] * xs[m ^ (1 << j)];
            s += cB[j] * (((m >> j) & 1) ? -xm : xm);
        }
        acc += xm * s;
    }
#pragma unroll
    for (int off = 16; off > 0; off >>= 1)
        acc += __shfl_down_sync(0xFFFFFFFFu, acc, off);
    if ((tid & 31) == 0) red[tid >> 5] = acc;
    __syncthreads();
    if (tid < 8) {
        float a = red[tid];
#pragma unroll
        for (int off = 4; off > 0; off >>= 1)
            a += __shfl_down_sync(0xFFu, a, off);
        if (tid == 0) out[row] = 1.f / (1.f + expf(-a));
    }
}

// ---------------------------------------------------------------------------
extern "C" void kernel_launch(void* const* d_in, const int* in_sizes, int n_in,
                              void* d_out, int out_size) {
    const float* x = nullptr;
    const float* bv = nullptr;
    const float* w = nullptr;
    const float* cw = nullptr;
    for (int i = 0; i < n_in; i++) {
        switch (in_sizes[i]) {
            case 2048 * 1024: x = (const float*)d_in[i]; break;
            case 1024:        bv = (const float*)d_in[i]; break;
            case 20:          w = (const float*)d_in[i]; break;
            case 90:          cw = (const float*)d_in[i]; break;
            default: break;  // P_tensor unused
        }
    }

    sim_kernel<0, true ><<<256, 512>>>(cw, 0);
    sim_kernel<1, false><<<256, 512>>>(cw, 0);
    sim_kernel<0, false><<<256, 512>>>(cw, 1);
    sim_kernel<1, false><<<256, 512>>>(cw, 1);
    sim_kernel<0, false><<<256, 512>>>(cw, 2);
    sim_kernel<1, false><<<256, 512>>>(cw, 2);
    logits_kernel<<<2048, 256>>>(x, bv, w, (float*)d_out);
}

// round 12
// speedup vs baseline: 1.2206x; 1.0027x over previous
#include <cuda_runtime.h>
#include <math.h>

// ---------------------------------------------------------------------------
// NISQ classifier via Pauli-transfer-matrix simulation.
// State c[p], p = 10 base-4 digits (slots). Qubit -> slot:
//   q:    0  1  2  3  4  5  6  7  8  9
//   slot: 0  2  3  4  5  1  6  7  8  9
// Stage A (KIND 0): slots 0-5 (bits 0-11)            -> CNOT 01,12,23,34,45
// Stage B (KIND 1): slots {0,1,6..9} (bits 0-3,12-19)-> CNOT 56,67,78,89,90
// Tail pruning: the 20 observables live in 9 KIND-1 tiles (bits4-11 in S9),
// so layer-2 stage B runs 9 blocks and layer-2 stage A stores only S9 data.
// ---------------------------------------------------------------------------

#define NSTATE (1 << 20)
__device__ float g_c[NSTATE];   // PTM state vector (4 MB)

// S9 = {0,1,3,4,12,16,48,64,192} as a 256-bit membership mask over bits4-11.
__device__ __constant__ unsigned long long PRMASK[4] =
    {0x000100000001101BULL, 1ULL, 0ULL, 1ULL};
__device__ __constant__ int TILE9[9] = {0, 1, 3, 4, 12, 16, 48, 64, 192};

// Bank swizzle: phys = u ^ SWf(u); linear over u bits 5-8 -> bank bits 0-4.
// Conflict-free for every pass pattern below (R4-verified).
__device__ __host__ constexpr unsigned SWf(unsigned u) {
    return ((((u >> 5) ^ (u >> 7)) & 1u))
         | ((((u >> 6)) & 1u) << 1)
         | ((((u >> 5) ^ (u >> 6)) & 1u) << 2)
         | ((((u >> 6) ^ (u >> 7)) & 1u) << 3)
         | ((((u >> 8)) & 1u) << 4);
}

// Build fused single-qubit PTM op: M = phase*amp*depol1*Rot (4x4, row I = e0)
__device__ __forceinline__ void build_M(float phi, float th, float om, float* M) {
    float cphi = cosf(phi), sphi = sinf(phi);
    float cth  = cosf(th),  sth  = sinf(th);
    float com  = cosf(om),  som  = sinf(om);
    float A[9]  = {com, -som, 0.f,  som, com, 0.f,  0.f, 0.f, 1.f};
    float Bm[9] = {cth, 0.f, sth,   0.f, 1.f, 0.f,  -sth, 0.f, cth};
    float C[9]  = {cphi, -sphi, 0.f, sphi, cphi, 0.f, 0.f, 0.f, 1.f};
    float AB[9], R[9];
#pragma unroll
    for (int i = 0; i < 3; i++)
#pragma unroll
        for (int j = 0; j < 3; j++) {
            float s = 0.f;
#pragma unroll
            for (int k = 0; k < 3; k++) s += A[i*3+k] * Bm[k*3+j];
            AB[i*3+j] = s;
        }
#pragma unroll
    for (int i = 0; i < 3; i++)
#pragma unroll
        for (int j = 0; j < 3; j++) {
            float s = 0.f;
#pragma unroll
            for (int k = 0; k < 3; k++) s += AB[i*3+k] * C[k*3+j];
            R[i*3+j] = s;
        }
    const float gamma = -expm1f(-1e-7f / 0.05f);
    const float gph   = -expm1f(-1e-7f / 0.07f);
    const float c1    = 1.0f - 4.0f * 0.001f / 3.0f;
    float sq = sqrtf((1.f - gamma) * (1.f - gph));
    float a1 = sq * c1, z1 = (1.f - gamma) * c1, g1 = gamma;
    M[0]  = 1.f; M[1]  = 0.f;       M[2]  = 0.f;       M[3]  = 0.f;
    M[4]  = 0.f; M[5]  = a1 * R[0]; M[6]  = a1 * R[1]; M[7]  = a1 * R[2];
    M[8]  = 0.f; M[9]  = a1 * R[3]; M[10] = a1 * R[4]; M[11] = a1 * R[5];
    M[12] = g1;  M[13] = z1 * R[6]; M[14] = z1 * R[7]; M[15] = z1 * R[8];
}

// Half-group pass (R9-verified): thread owns rows {0,3} (h=0) or {1,2} (h=1).
template<int PC, int PT, bool HASMT>
__device__ __forceinline__ void hpass(float* __restrict__ t,
                                      const float* __restrict__ MT,
                                      float aN, float zN, float gN) {
    constexpr int sc = 2 * PC, st = 2 * PT;
    constexpr int plo  = (sc < st) ? sc : st;
    constexpr int phi_ = (sc < st) ? st : sc;
    constexpr int midw = phi_ - plo - 2;
    constexpr unsigned C1 = (1u << st) ^ SWf(1u << st);
    constexpr unsigned C2 = (2u << st) ^ SWf(2u << st);
    constexpr unsigned C3 = (3u << st) ^ SWf(3u << st);

    unsigned tid = threadIdx.x;
    unsigned g   = tid & 255u;
    unsigned h   = tid >> 8;           // warp-uniform
    unsigned rA  = h;
    unsigned rB  = 3u - h;

    unsigned lo   = g & ((1u << plo) - 1u);
    unsigned rest = g >> plo;
    unsigned mid  = rest & ((1u << midw) - 1u);
    unsigned hi   = rest >> midw;
    unsigned base = lo | (mid << (plo + 2)) | (hi << (phi_ + 2));
    unsigned bA = base | (rA << sc);
    unsigned bB = base | (rB << sc);
    unsigned pA = bA ^ SWf(bA);
    unsigned pB = bB ^ SWf(bB);

    float a0 = t[pA], a1 = t[pA ^ C1], a2 = t[pA ^ C2], a3 = t[pA ^ C3];
    float b0 = t[pB], b1 = t[pB ^ C1], b2 = t[pB ^ C2], b3 = t[pB ^ C3];

    if (HASMT) {
        float x1 = MT[5]*a1 + MT[6]*a2 + MT[7]*a3;
        float x2 = MT[9]*a1 + MT[10]*a2 + MT[11]*a3;
        float x3 = MT[12]*a0 + MT[13]*a1 + MT[14]*a2 + MT[15]*a3;
        a1 = x1; a2 = x2; a3 = x3;
        float y1 = MT[5]*b1 + MT[6]*b2 + MT[7]*b3;
        float y2 = MT[9]*b1 + MT[10]*b2 + MT[11]*b3;
        float y3 = MT[12]*b0 + MT[13]*b1 + MT[14]*b2 + MT[15]*b3;
        b1 = y1; b2 = y2; b3 = y3;
    }

    float A0, A1, A2, A3, B0, B1, B2, B3;
    if (h == 0) {
        A0 = a0; A1 = a1; A2 = b2; A3 = b3;
        B0 = b0; B1 = b1; B2 = a2; B3 = a3;
        float n0 = gN * A0 + zN * B0;
        float n1 = gN * A1 + zN * B1;
        float n2 = gN * A2 + zN * B2;
        float n3 = gN * A3 + zN * B3;
        B0 = n0; B1 = n1; B2 = n2; B3 = n3;
    } else {
        A0 = aN * a1; A1 = aN * a0; A2 = aN * b3; A3 = -aN * b2;
        B0 = aN * b1; B1 = aN * b0; B2 = -aN * a3; B3 = aN * a2;
    }
    float oA3 = gN * A0 + zN * A3;
    float oB3 = gN * B0 + zN * B3;
    t[pA]      = A0;
    t[pA ^ C1] = aN * A1;
    t[pA ^ C2] = aN * A2;
    t[pA ^ C3] = oA3;
    t[pB]      = B0;
    t[pB ^ C1] = aN * B1;
    t[pB ^ C2] = aN * B2;
    t[pB ^ C3] = oB3;
}

template<int KIND>
__device__ __forceinline__ unsigned gidx(unsigned u, unsigned tile) {
    if (KIND == 0) return u | (tile << 12);
    else           return (u & 15u) | (tile << 4) | ((u >> 4) << 12);
}

// ---------------------------------------------------------------------------
// Sim kernel: 512 threads, 4096-float swizzled smem tile.
// PRUNE (KIND 0, last layer): store only elements with bits4-11 in S9.
// REMAP (KIND 1, last layer): grid=9, block -> TILE9 tile.
// ---------------------------------------------------------------------------
template<int KIND, bool INIT, bool PRUNE, bool REMAP>
__global__ __launch_bounds__(512) void sim_kernel(const float* __restrict__ wts,
                                                  int layer) {
    __shared__ float t[4096];
    __shared__ float sM[10][16];
    unsigned blk = REMAP ? (unsigned)TILE9[blockIdx.x] : blockIdx.x;
    unsigned tid = threadIdx.x;

    // Issue global loads first so they overlap with build_M trig.
    float4 r[2];
#pragma unroll
    for (int i = 0; i < 2; i++) {
        unsigned u = (tid + i * 512u) * 4u;
        if (INIT) {
            unsigned p = gidx<KIND>(u, blk);
            float v = ((((p >> 1) ^ p) & 0x55555u) == 0u) ? 1.0f : 0.0f;
            r[i].x = v; r[i].y = 0.f; r[i].z = 0.f; r[i].w = v;
        } else {
            r[i] = *(const float4*)&g_c[gidx<KIND>(u, blk)];
        }
    }
    if (tid < 10) {
        const float* a = wts + (layer * 10 + (int)tid) * 3;
        build_M(a[0], a[1], a[2], sM[tid]);
    }
    __syncthreads();

#pragma unroll
    for (int i = 0; i < 2; i++) {
        unsigned u = (tid + i * 512u) * 4u;
        float4 v = r[i];
        if (KIND == 0) {   // fold M0 (slot 0 = bits 0-1 of tile index)
            float x1 = sM[0][5]*v.y + sM[0][6]*v.z + sM[0][7]*v.w;
            float x2 = sM[0][9]*v.y + sM[0][10]*v.z + sM[0][11]*v.w;
            float x3 = sM[0][12]*v.x + sM[0][13]*v.y + sM[0][14]*v.z + sM[0][15]*v.w;
            v.y = x1; v.z = x2; v.w = x3;
        }
        unsigned sw = SWf(u);
        t[(u + 0) ^ sw] = v.x;
        t[(u + 1) ^ sw] = v.y;
        t[(u + 2) ^ sw] = v.z;
        t[(u + 3) ^ sw] = v.w;
    }
    __syncthreads();

    const float gamma = -expm1f(-1e-7f / 0.05f);
    const float gph   = -expm1f(-1e-7f / 0.07f);
    const float c2    = 1.0f - 4.0f * 0.01f / 3.0f;
    const float aN = sqrtf((1.f - gamma) * (1.f - gph)) * c2;
    const float zN = (1.f - gamma) * c2;
    const float gN = gamma;

    if (KIND == 0) {
        hpass<0, 2, true>(t, sM[1], aN, zN, gN); __syncthreads(); // M1, CNOT(q0,q1)
        hpass<2, 3, true>(t, sM[2], aN, zN, gN); __syncthreads(); // M2, CNOT(q1,q2)
        hpass<3, 4, true>(t, sM[3], aN, zN, gN); __syncthreads(); // M3, CNOT(q2,q3)
        hpass<4, 5, true>(t, sM[4], aN, zN, gN); __syncthreads(); // M4, CNOT(q3,q4)
        hpass<5, 1, true>(t, sM[5], aN, zN, gN); __syncthreads(); // M5, CNOT(q4,q5)
    } else {
        hpass<1, 2, true >(t, sM[6], aN, zN, gN); __syncthreads(); // M6, CNOT(q5,q6)
        hpass<2, 3, true >(t, sM[7], aN, zN, gN); __syncthreads(); // M7, CNOT(q6,q7)
        hpass<3, 4, true >(t, sM[8], aN, zN, gN); __syncthreads(); // M8, CNOT(q7,q8)
        hpass<4, 5, true >(t, sM[9], aN, zN, gN); __syncthreads(); // M9, CNOT(q8,q9)
        hpass<5, 0, false>(t, 0,     aN, zN, gN); __syncthreads(); // CNOT(q9,q0)
    }

#pragma unroll
    for (int i = 0; i < 2; i++) {
        unsigned u = (tid + i * 512u) * 4u;
        if (PRUNE) {   // KIND 0: element bits4-11 = u[4:11], fixed per float4
            unsigned vsel = (u >> 4) & 0xFFu;
            if (!((PRMASK[vsel >> 6] >> (vsel & 63u)) & 1ull)) continue;
        }
        unsigned sw = SWf(u);
        float4 v;
        v.x = t[(u + 0) ^ sw];
        v.y = t[(u + 1) ^ sw];
        v.z = t[(u + 2) ^ sw];
        v.w = t[(u + 3) ^ sw];
        *(float4*)&g_c[gidx<KIND>(u, blk)] = v;
    }
}

// ---------------------------------------------------------------------------
// Logits: one block per batch row.
// ---------------------------------------------------------------------------
__global__ __launch_bounds__(256) void logits_kernel(
    const float* __restrict__ x, const float* __restrict__ bvec,
    const float* __restrict__ w, float* __restrict__ out) {
    __shared__ float xs[1024];
    __shared__ float cA[10], cB[10];
    __shared__ float red[8];
    int row = blockIdx.x, tid = threadIdx.x;

    for (int m = tid; m < 1024; m += 256)
        xs[m] = x[row * 1024 + m] + bvec[m];

    if (tid < 10) {
        const int slot_of_q[10] = {0, 2, 3, 4, 5, 1, 6, 7, 8, 9};
        int q = tid;
        int j = 9 - q;
        int s2 = 2 * slot_of_q[q];
        cA[j] = w[2 * q] * g_c[1u << s2];
        cB[j] = w[2 * q + 1] * 0.96f * g_c[3u << s2];   // readout: 1-2*0.02
    }
    __syncthreads();

    float acc = 0.f;
    for (int m = tid; m < 1024; m += 256) {
        float xm = xs[m];
        float s = 0.f;
#pragma unroll
        for (int j = 0; j < 10; j++) {
            s += cA[j] * xs[m ^ (1 << j)];
            s += cB[j] * (((m >> j) & 1) ? -xm : xm);
        }
        acc += xm * s;
    }
#pragma unroll
    for (int off = 16; off > 0; off >>= 1)
        acc += __shfl_down_sync(0xFFFFFFFFu, acc, off);
    if ((tid & 31) == 0) red[tid >> 5] = acc;
    __syncthreads();
    if (tid < 8) {
        float a = red[tid];
#pragma unroll
        for (int off = 4; off > 0; off >>= 1)
            a += __shfl_down_sync(0xFFu, a, off);
        if (tid == 0) out[row] = 1.f / (1.f + expf(-a));
    }
}

// ---------------------------------------------------------------------------
extern "C" void kernel_launch(void* const* d_in, const int* in_sizes, int n_in,
                              void* d_out, int out_size) {
    const float* x = nullptr;
    const float* bv = nullptr;
    const float* w = nullptr;
    const float* cw = nullptr;
    for (int i = 0; i < n_in; i++) {
        switch (in_sizes[i]) {
            case 2048 * 1024: x = (const float*)d_in[i]; break;
            case 1024:        bv = (const float*)d_in[i]; break;
            case 20:          w = (const float*)d_in[i]; break;
            case 90:          cw = (const float*)d_in[i]; break;
            default: break;  // P_tensor unused
        }
    }

    sim_kernel<0, true,  false, false><<<256, 512>>>(cw, 0);
    sim_kernel<1, false, false, false><<<256, 512>>>(cw, 0);
    sim_kernel<0, false, false, false><<<256, 512>>>(cw, 1);
    sim_kernel<1, false, false, false><<<256, 512>>>(cw, 1);
    sim_kernel<0, false, true,  false><<<256, 512>>>(cw, 2);   // pruned stores
    sim_kernel<1, false, false, true ><<<9,   512>>>(cw, 2);   // 9 observable tiles
    logits_kernel<<<2048, 256>>>(x, bv, w, (float*)d_out);
}

// round 13
// speedup vs baseline: 1.4008x; 1.1477x over previous
#include <cuda_runtime.h>
#include <math.h>

// ---------------------------------------------------------------------------
// NISQ classifier via Pauli-transfer-matrix simulation.
// State c[p], p = 10 base-4 digits (slots). Qubit -> slot:
//   q:    0  1  2  3  4  5  6  7  8  9
//   slot: 0  2  3  4  5  1  6  7  8  9
// Stage A (KIND 0): slots 0-5 (bits 0-11)            -> CNOT 01,12,23,34,45
// Stage B (KIND 1): slots {0,1,6..9} (bits 0-3,12-19)-> CNOT 56,67,78,89,90
// K1 = sim A0 (blocks 0-255) + feats (blocks 256-511, warp-per-row, reg-only).
// B2 (9 tiles) emits we[20] = w*0.96^?*tr(P rho) directly; final = dot+sigmoid.
// ---------------------------------------------------------------------------

#define NSTATE (1 << 20)
__device__ float g_c[NSTATE];                       // PTM state vector (4 MB)
__device__ __align__(16) float g_feats[2048 * 20];  // per-row Pauli features
__device__ float g_we[20];                          // w[k] * exps[k]

// S9 = {0,1,3,4,12,16,48,64,192}: 256-bit membership mask over bits4-11.
__device__ __constant__ unsigned long long PRMASK[4] =
    {0x000100000001101BULL, 1ULL, 0ULL, 1ULL};
__device__ __constant__ int TILE9[9] = {0, 1, 3, 4, 12, 16, 48, 64, 192};

// Observable table, k = 0..9: A-part (X_q, j=k, q=9-k); k = 10..19: Z-part.
// T = KIND1 tile (bits4-11 of global idx), U = within-tile index, W = w index.
__device__ __constant__ short OBS_T[20] =
    {0, 0, 0, 0, 0, 64, 16, 4, 1, 0,   0, 0, 0, 0, 0, 192, 48, 12, 3, 0};
__device__ __constant__ short OBS_U[20] =
    {1024, 256, 64, 16, 4, 0, 0, 0, 0, 1,   3072, 768, 192, 48, 12, 0, 0, 0, 0, 3};
__device__ __constant__ char OBS_W[20] =
    {18, 16, 14, 12, 10, 8, 6, 4, 2, 0,   19, 17, 15, 13, 11, 9, 7, 5, 3, 1};

// Bank swizzle (R4-verified conflict-free for all pass patterns).
__device__ __host__ constexpr unsigned SWf(unsigned u) {
    return ((((u >> 5) ^ (u >> 7)) & 1u))
         | ((((u >> 6)) & 1u) << 1)
         | ((((u >> 5) ^ (u >> 6)) & 1u) << 2)
         | ((((u >> 6) ^ (u >> 7)) & 1u) << 3)
         | ((((u >> 8)) & 1u) << 4);
}

// Build fused single-qubit PTM op: M = phase*amp*depol1*Rot (4x4, row I = e0)
__device__ __forceinline__ void build_M(float phi, float th, float om, float* M) {
    float cphi = cosf(phi), sphi = sinf(phi);
    float cth  = cosf(th),  sth  = sinf(th);
    float com  = cosf(om),  som  = sinf(om);
    float A[9]  = {com, -som, 0.f,  som, com, 0.f,  0.f, 0.f, 1.f};
    float Bm[9] = {cth, 0.f, sth,   0.f, 1.f, 0.f,  -sth, 0.f, cth};
    float C[9]  = {cphi, -sphi, 0.f, sphi, cphi, 0.f, 0.f, 0.f, 1.f};
    float AB[9], R[9];
#pragma unroll
    for (int i = 0; i < 3; i++)
#pragma unroll
        for (int j = 0; j < 3; j++) {
            float s = 0.f;
#pragma unroll
            for (int k = 0; k < 3; k++) s += A[i*3+k] * Bm[k*3+j];
            AB[i*3+j] = s;
        }
#pragma unroll
    for (int i = 0; i < 3; i++)
#pragma unroll
        for (int j = 0; j < 3; j++) {
            float s = 0.f;
#pragma unroll
            for (int k = 0; k < 3; k++) s += AB[i*3+k] * C[k*3+j];
            R[i*3+j] = s;
        }
    const float gamma = -expm1f(-1e-7f / 0.05f);
    const float gph   = -expm1f(-1e-7f / 0.07f);
    const float c1    = 1.0f - 4.0f * 0.001f / 3.0f;
    float sq = sqrtf((1.f - gamma) * (1.f - gph));
    float a1 = sq * c1, z1 = (1.f - gamma) * c1, g1 = gamma;
    M[0]  = 1.f; M[1]  = 0.f;       M[2]  = 0.f;       M[3]  = 0.f;
    M[4]  = 0.f; M[5]  = a1 * R[0]; M[6]  = a1 * R[1]; M[7]  = a1 * R[2];
    M[8]  = 0.f; M[9]  = a1 * R[3]; M[10] = a1 * R[4]; M[11] = a1 * R[5];
    M[12] = g1;  M[13] = z1 * R[6]; M[14] = z1 * R[7]; M[15] = z1 * R[8];
}

// Fused pass (R4, best-measured): optional single ops, CNOT signed
// permutation, per-wire 2-qubit noise. One 16-elem group per thread (256 thr).
template<int PC, int PT, bool HASMT, bool HASMC>
__device__ __forceinline__ void pass(float* t,
                                     const float* __restrict__ MT,
                                     const float* __restrict__ MC,
                                     float aN, float zN, float gN) {
    constexpr int sc = 2 * PC, st = 2 * PT;
    constexpr int plo  = (sc < st) ? sc : st;
    constexpr int phi_ = (sc < st) ? st : sc;
    constexpr int midw = phi_ - plo - 2;
    unsigned g    = threadIdx.x;
    unsigned lo   = g & ((1u << plo) - 1u);
    unsigned rest = g >> plo;
    unsigned mid  = rest & ((1u << midw) - 1u);
    unsigned hi   = rest >> midw;
    unsigned base = lo | (mid << (plo + 2)) | (hi << (phi_ + 2));
    unsigned pb   = base ^ SWf(base);

    float v[16];
#pragma unroll
    for (int dc = 0; dc < 4; dc++)
#pragma unroll
        for (int dt = 0; dt < 4; dt++) {
            unsigned off = ((unsigned)dc << sc) | ((unsigned)dt << st);
            v[dc * 4 + dt] = t[pb ^ off ^ SWf(off)];
        }

    if (HASMT) {
#pragma unroll
        for (int dc = 0; dc < 4; dc++) {
            float v0 = v[dc*4+0], v1 = v[dc*4+1], v2 = v[dc*4+2], v3 = v[dc*4+3];
            v[dc*4+1] = MT[5]  * v1 + MT[6]  * v2 + MT[7]  * v3;
            v[dc*4+2] = MT[9]  * v1 + MT[10] * v2 + MT[11] * v3;
            v[dc*4+3] = MT[12] * v0 + MT[13] * v1 + MT[14] * v2 + MT[15] * v3;
        }
    }
    if (HASMC) {
#pragma unroll
        for (int dt = 0; dt < 4; dt++) {
            float v0 = v[0+dt], v1 = v[4+dt], v2 = v[8+dt], v3 = v[12+dt];
            v[4 + dt]  = MC[5]  * v1 + MC[6]  * v2 + MC[7]  * v3;
            v[8 + dt]  = MC[9]  * v1 + MC[10] * v2 + MC[11] * v3;
            v[12 + dt] = MC[12] * v0 + MC[13] * v1 + MC[14] * v2 + MC[15] * v3;
        }
    }

    const int tbl[16] = {0, 1, 14, 15, 5, 4, 11, 10, 9, 8, 7, 6, 12, 13, 2, 3};
    float w_[16];
#pragma unroll
    for (int i = 0; i < 16; i++) w_[i] = v[tbl[i]];
    w_[7]  = -w_[7];
    w_[10] = -w_[10];
#pragma unroll
    for (int dt = 0; dt < 4; dt++) {
        float u0 = w_[0+dt], u1 = w_[4+dt], u2 = w_[8+dt], u3 = w_[12+dt];
        w_[4 + dt]  = aN * u1;
        w_[8 + dt]  = aN * u2;
        w_[12 + dt] = gN * u0 + zN * u3;
    }
#pragma unroll
    for (int dc = 0; dc < 4; dc++) {
        float u0 = w_[dc*4+0], u1 = w_[dc*4+1], u2 = w_[dc*4+2], u3 = w_[dc*4+3];
        w_[dc*4+1] = aN * u1;
        w_[dc*4+2] = aN * u2;
        w_[dc*4+3] = gN * u0 + zN * u3;
    }
#pragma unroll
    for (int dc = 0; dc < 4; dc++)
#pragma unroll
        for (int dt = 0; dt < 4; dt++) {
            unsigned off = ((unsigned)dc << sc) | ((unsigned)dt << st);
            t[pb ^ off ^ SWf(off)] = w_[dc * 4 + dt];
        }
}

template<int KIND>
__device__ __forceinline__ unsigned gidx(unsigned u, unsigned tile) {
    if (KIND == 0) return u | (tile << 12);
    else           return (u & 15u) | (tile << 4) | ((u >> 4) << 12);
}

// One tile through a stage (R4 body, 256 threads).
template<int KIND, bool INIT, bool PRUNE, bool STORE>
__device__ __forceinline__ void stage_body(const float* __restrict__ wts,
                                           int layer, unsigned blk,
                                           float* t, float sM[10][16]) {
    unsigned tid = threadIdx.x;
    if (INIT) {
        for (unsigned u = tid; u < 4096; u += 256) {
            unsigned p = gidx<KIND>(u, blk);
            t[u ^ SWf(u)] = ((((p >> 1) ^ p) & 0x55555u) == 0u) ? 1.0f : 0.0f;
        }
    } else {
#pragma unroll
        for (int i = 0; i < 4; i++) {
            unsigned u = (tid + i * 256u) * 4u;
            float4 r = *(const float4*)&g_c[gidx<KIND>(u, blk)];
            unsigned sw = SWf(u);
            t[(u + 0) ^ sw] = r.x;
            t[(u + 1) ^ sw] = r.y;
            t[(u + 2) ^ sw] = r.z;
            t[(u + 3) ^ sw] = r.w;
        }
    }
    if (tid < 10) {
        const float* a = wts + (layer * 10 + (int)tid) * 3;
        build_M(a[0], a[1], a[2], sM[tid]);
    }
    __syncthreads();

    const float gamma = -expm1f(-1e-7f / 0.05f);
    const float gph   = -expm1f(-1e-7f / 0.07f);
    const float c2    = 1.0f - 4.0f * 0.01f / 3.0f;
    const float aN = sqrtf((1.f - gamma) * (1.f - gph)) * c2;
    const float zN = (1.f - gamma) * c2;
    const float gN = gamma;

    if (KIND == 0) {
        pass<0, 2, true, true >(t, sM[1], sM[0], aN, zN, gN); __syncthreads();
        pass<2, 3, true, false>(t, sM[2], 0,     aN, zN, gN); __syncthreads();
        pass<3, 4, true, false>(t, sM[3], 0,     aN, zN, gN); __syncthreads();
        pass<4, 5, true, false>(t, sM[4], 0,     aN, zN, gN); __syncthreads();
        pass<5, 1, true, false>(t, sM[5], 0,     aN, zN, gN); __syncthreads();
    } else {
        pass<1, 2, true, false>(t, sM[6], 0, aN, zN, gN); __syncthreads();
        pass<2, 3, true, false>(t, sM[7], 0, aN, zN, gN); __syncthreads();
        pass<3, 4, true, false>(t, sM[8], 0, aN, zN, gN); __syncthreads();
        pass<4, 5, true, false>(t, sM[9], 0, aN, zN, gN); __syncthreads();
        pass<5, 0, false,false>(t, 0,     0, aN, zN, gN); __syncthreads();
    }

    if (STORE) {
#pragma unroll
        for (int i = 0; i < 4; i++) {
            unsigned u = (tid + i * 256u) * 4u;
            if (PRUNE) {
                unsigned vsel = (u >> 4) & 0xFFu;
                if (!((PRMASK[vsel >> 6] >> (vsel & 63u)) & 1ull)) continue;
            }
            unsigned sw = SWf(u);
            float4 r;
            r.x = t[(u + 0) ^ sw];
            r.y = t[(u + 1) ^ sw];
            r.z = t[(u + 2) ^ sw];
            r.w = t[(u + 3) ^ sw];
            *(float4*)&g_c[gidx<KIND>(u, blk)] = r;
        }
    }
}

// ---------------------------------------------------------------------------
// feats: warp-per-row, register-resident, no smem/syncs.
// Thread holds 8 quads: m = 4*(lane + 32*t).  j=0,1 within quad; j=7,8,9
// across own t-quads; j=2..6 via shfl_xor; Z-part from signed squares.
// ---------------------------------------------------------------------------
__device__ __forceinline__ float dot4(const float* a, const float* b) {
    return a[0]*b[0] + a[1]*b[1] + a[2]*b[2] + a[3]*b[3];
}

__device__ void feats_body(const float* __restrict__ x,
                           const float* __restrict__ bvec, int fblk) {
    int lane = threadIdx.x & 31;
    int row  = fblk * 8 + (threadIdx.x >> 5);
    const float4* xr = (const float4*)(x + row * 1024);
    const float4* br = (const float4*)bvec;

    float e[8][4];
#pragma unroll
    for (int t = 0; t < 8; t++) {
        float4 xv = xr[lane + 32 * t];
        float4 bb = br[lane + 32 * t];
        e[t][0] = xv.x + bb.x; e[t][1] = xv.y + bb.y;
        e[t][2] = xv.z + bb.z; e[t][3] = xv.w + bb.w;
    }

    float fA[10], fZ[10];
#pragma unroll
    for (int j = 0; j < 10; j++) { fA[j] = 0.f; fZ[j] = 0.f; }
    float Stot = 0.f;

#pragma unroll
    for (int t = 0; t < 8; t++) {
        float s0 = e[t][0]*e[t][0], s1 = e[t][1]*e[t][1];
        float s2 = e[t][2]*e[t][2], s3 = e[t][3]*e[t][3];
        float St = (s0 + s1) + (s2 + s3);
        Stot += St;
        fZ[0] += (s0 - s1) + (s2 - s3);
        fZ[1] += (s0 + s1) - (s2 + s3);
        fZ[7] += (t & 1) ? -St : St;
        fZ[8] += (t & 2) ? -St : St;
        fZ[9] += (t & 4) ? -St : St;
        fA[0] += 2.f * (e[t][0]*e[t][1] + e[t][2]*e[t][3]);
        fA[1] += 2.f * (e[t][0]*e[t][2] + e[t][1]*e[t][3]);
    }
#pragma unroll
    for (int j = 2; j <= 6; j++)
        fZ[j] = ((lane >> (j - 2)) & 1) ? -Stot : Stot;

    fA[7] = 2.f * (dot4(e[0],e[1]) + dot4(e[2],e[3]) + dot4(e[4],e[5]) + dot4(e[6],e[7]));
    fA[8] = 2.f * (dot4(e[0],e[2]) + dot4(e[1],e[3]) + dot4(e[4],e[6]) + dot4(e[5],e[7]));
    fA[9] = 2.f * (dot4(e[0],e[4]) + dot4(e[1],e[5]) + dot4(e[2],e[6]) + dot4(e[3],e[7]));

#pragma unroll
    for (int j = 2; j <= 6; j++) {
        int b = 1 << (j - 2);
        float acc = 0.f;
#pragma unroll
        for (int t = 0; t < 8; t++)
#pragma unroll
            for (int k = 0; k < 4; k++) {
                float nb = __shfl_xor_sync(0xFFFFFFFFu, e[t][k], b);
                acc += e[t][k] * nb;
            }
        fA[j] = acc;
    }

    // warp-reduce all 20 accumulators
#pragma unroll
    for (int j = 0; j < 10; j++) {
#pragma unroll
        for (int off = 16; off > 0; off >>= 1) {
            fA[j] += __shfl_down_sync(0xFFFFFFFFu, fA[j], off);
            fZ[j] += __shfl_down_sync(0xFFFFFFFFu, fZ[j], off);
        }
    }
    if (lane == 0) {
#pragma unroll
        for (int j = 0; j < 10; j++) {
            g_feats[row * 20 + j]      = fA[j];
            g_feats[row * 20 + 10 + j] = fZ[j];
        }
    }
}

// ---------------------------------------------------------------------------
// K1: blocks 0-255 = sim stage A0 (INIT); blocks 256-511 = feats (8 rows ea).
// ---------------------------------------------------------------------------
__global__ __launch_bounds__(256) void k1_kernel(const float* __restrict__ wts,
                                                 const float* __restrict__ x,
                                                 const float* __restrict__ bvec) {
    __shared__ float t[4096];
    __shared__ float sM[10][16];
    if (blockIdx.x < 256) {
        stage_body<0, true, false, true>(wts, 0, blockIdx.x, t, sM);
    } else {
        feats_body(x, bvec, (int)blockIdx.x - 256);
    }
}

// Generic sim stage kernel. REMAP: 9 observable tiles; emits g_we, no stores.
template<int KIND, bool PRUNE, bool REMAP>
__global__ __launch_bounds__(256) void sim_kernel(const float* __restrict__ wts,
                                                  const float* __restrict__ w,
                                                  int layer) {
    __shared__ float t[4096];
    __shared__ float sM[10][16];
    unsigned blk = REMAP ? (unsigned)TILE9[blockIdx.x] : blockIdx.x;
    stage_body<KIND, false, PRUNE, !REMAP>(wts, layer, blk, t, sM);
    if (REMAP) {
        unsigned tid = threadIdx.x;
        if (tid < 20 && (unsigned)OBS_T[tid] == blk) {
            unsigned u = (unsigned)OBS_U[tid];
            float v = t[u ^ SWf(u)];
            float coef = w[(int)OBS_W[tid]] * (tid < 10 ? 1.0f : 0.96f);
            g_we[tid] = coef * v;
        }
    }
}

// Final: logit[row] = dot(feats[row], we); sigmoid.
__global__ __launch_bounds__(256) void final_kernel(float* __restrict__ out) {
    int row = blockIdx.x * 256 + threadIdx.x;
    const float4* f = (const float4*)(g_feats + row * 20);
    float acc = 0.f;
#pragma unroll
    for (int i = 0; i < 5; i++) {
        float4 v = f[i];
        acc += v.x * g_we[i*4+0] + v.y * g_we[i*4+1]
             + v.z * g_we[i*4+2] + v.w * g_we[i*4+3];
    }
    out[row] = 1.f / (1.f + expf(-acc));
}

// ---------------------------------------------------------------------------
extern "C" void kernel_launch(void* const* d_in, const int* in_sizes, int n_in,
                              void* d_out, int out_size) {
    const float* x = nullptr;
    const float* bv = nullptr;
    const float* w = nullptr;
    const float* cw = nullptr;
    for (int i = 0; i < n_in; i++) {
        switch (in_sizes[i]) {
            case 2048 * 1024: x = (const float*)d_in[i]; break;
            case 1024:        bv = (const float*)d_in[i]; break;
            case 20:          w = (const float*)d_in[i]; break;
            case 90:          cw = (const float*)d_in[i]; break;
            default: break;  // P_tensor unused
        }
    }

    k1_kernel<<<512, 256>>>(cw, x, bv);                       // A0 + feats
    sim_kernel<1, false, false><<<256, 256>>>(cw, w, 0);      // B0
    sim_kernel<0, false, false><<<256, 256>>>(cw, w, 1);      // A1
    sim_kernel<1, false, false><<<256, 256>>>(cw, w, 1);      // B1
    sim_kernel<0, true,  false><<<256, 256>>>(cw, w, 2);      // A2 (pruned)
    sim_kernel<1, false, true ><<<9,   256>>>(cw, w, 2);      // B2 -> g_we
    final_kernel<<<8, 256>>>((float*)d_out);                  // dot + sigmoid
}

// round 15
// speedup vs baseline: 1.5551x; 1.1101x over previous
#include <cuda_runtime.h>
#include <math.h>

// ---------------------------------------------------------------------------
// NISQ classifier via Pauli-transfer-matrix simulation.
// State c[p], p = 10 base-4 digits (slots). Qubit -> slot:
//   q:    0  1  2  3  4  5  6  7  8  9
//   slot: 0  2  3  4  5  1  6  7  8  9
// Stage A (KIND 0): slots 0-5 (bits 0-11)            -> CNOT 01,12,23,34,45
// Stage B (KIND 1): slots {0,1,6..9} (bits 0-3,12-19)-> CNOT 56,67,78,89,90
// Sparsity: init state nonzero only where all digits in {I,Z} -> A0 has just
// 16 nonzero tiles (16 blocks); B0 loads only live elements (masked).
// Tail: A2 stores only S9 data; B2 (9 tiles) emits we[20]; final = dot+sigmoid.
// ---------------------------------------------------------------------------

#define NSTATE (1 << 20)
__device__ float g_c[NSTATE];                       // PTM state vector (4 MB)
__device__ __align__(16) float g_feats[2048 * 20];  // per-row Pauli features
__device__ float g_we[20];                          // w[k] * exps[k]

// S9 = {0,1,3,4,12,16,48,64,192}: 256-bit membership mask over bits4-11.
__device__ __constant__ unsigned long long PRMASK[4] =
    {0x000100000001101BULL, 1ULL, 0ULL, 1ULL};
__device__ __constant__ int TILE9[9] = {0, 1, 3, 4, 12, 16, 48, 64, 192};

// Observable table (R12-verified): k=0..9 X-part, k=10..19 Z-part.
__device__ __constant__ short OBS_T[20] =
    {0, 0, 0, 0, 0, 64, 16, 4, 1, 0,   0, 0, 0, 0, 0, 192, 48, 12, 3, 0};
__device__ __constant__ short OBS_U[20] =
    {1024, 256, 64, 16, 4, 0, 0, 0, 0, 1,   3072, 768, 192, 48, 12, 0, 0, 0, 0, 3};
__device__ __constant__ char OBS_W[20] =
    {18, 16, 14, 12, 10, 8, 6, 4, 2, 0,   19, 17, 15, 13, 11, 9, 7, 5, 3, 1};

// Bank swizzle (R4-verified conflict-free for all pass patterns).
__device__ __host__ constexpr unsigned SWf(unsigned u) {
    return ((((u >> 5) ^ (u >> 7)) & 1u))
         | ((((u >> 6)) & 1u) << 1)
         | ((((u >> 5) ^ (u >> 6)) & 1u) << 2)
         | ((((u >> 6) ^ (u >> 7)) & 1u) << 3)
         | ((((u >> 8)) & 1u) << 4);
}

// Build fused single-qubit PTM op: M = phase*amp*depol1*Rot (4x4, row I = e0)
__device__ __forceinline__ void build_M(float phi, float th, float om, float* M) {
    float cphi = cosf(phi), sphi = sinf(phi);
    float cth  = cosf(th),  sth  = sinf(th);
    float com  = cosf(om),  som  = sinf(om);
    float A[9]  = {com, -som, 0.f,  som, com, 0.f,  0.f, 0.f, 1.f};
    float Bm[9] = {cth, 0.f, sth,   0.f, 1.f, 0.f,  -sth, 0.f, cth};
    float C[9]  = {cphi, -sphi, 0.f, sphi, cphi, 0.f, 0.f, 0.f, 1.f};
    float AB[9], R[9];
#pragma unroll
    for (int i = 0; i < 3; i++)
#pragma unroll
        for (int j = 0; j < 3; j++) {
            float s = 0.f;
#pragma unroll
            for (int k = 0; k < 3; k++) s += A[i*3+k] * Bm[k*3+j];
            AB[i*3+j] = s;
        }
#pragma unroll
    for (int i = 0; i < 3; i++)
#pragma unroll
        for (int j = 0; j < 3; j++) {
            float s = 0.f;
#pragma unroll
            for (int k = 0; k < 3; k++) s += AB[i*3+k] * C[k*3+j];
            R[i*3+j] = s;
        }
    const float gamma = -expm1f(-1e-7f / 0.05f);
    const float gph   = -expm1f(-1e-7f / 0.07f);
    const float c1    = 1.0f - 4.0f * 0.001f / 3.0f;
    float sq = sqrtf((1.f - gamma) * (1.f - gph));
    float a1 = sq * c1, z1 = (1.f - gamma) * c1, g1 = gamma;
    M[0]  = 1.f; M[1]  = 0.f;       M[2]  = 0.f;       M[3]  = 0.f;
    M[4]  = 0.f; M[5]  = a1 * R[0]; M[6]  = a1 * R[1]; M[7]  = a1 * R[2];
    M[8]  = 0.f; M[9]  = a1 * R[3]; M[10] = a1 * R[4]; M[11] = a1 * R[5];
    M[12] = g1;  M[13] = z1 * R[6]; M[14] = z1 * R[7]; M[15] = z1 * R[8];
}

// Fused pass (R4, best-measured): optional single ops, CNOT signed
// permutation, per-wire 2-qubit noise. One 16-elem group per thread (256 thr).
template<int PC, int PT, bool HASMT, bool HASMC>
__device__ __forceinline__ void pass(float* t,
                                     const float* __restrict__ MT,
                                     const float* __restrict__ MC,
                                     float aN, float zN, float gN) {
    constexpr int sc = 2 * PC, st = 2 * PT;
    constexpr int plo  = (sc < st) ? sc : st;
    constexpr int phi_ = (sc < st) ? st : sc;
    constexpr int midw = phi_ - plo - 2;
    unsigned g    = threadIdx.x;
    unsigned lo   = g & ((1u << plo) - 1u);
    unsigned rest = g >> plo;
    unsigned mid  = rest & ((1u << midw) - 1u);
    unsigned hi   = rest >> midw;
    unsigned base = lo | (mid << (plo + 2)) | (hi << (phi_ + 2));
    unsigned pb   = base ^ SWf(base);

    float v[16];
#pragma unroll
    for (int dc = 0; dc < 4; dc++)
#pragma unroll
        for (int dt = 0; dt < 4; dt++) {
            unsigned off = ((unsigned)dc << sc) | ((unsigned)dt << st);
            v[dc * 4 + dt] = t[pb ^ off ^ SWf(off)];
        }

    if (HASMT) {
#pragma unroll
        for (int dc = 0; dc < 4; dc++) {
            float v0 = v[dc*4+0], v1 = v[dc*4+1], v2 = v[dc*4+2], v3 = v[dc*4+3];
            v[dc*4+1] = MT[5]  * v1 + MT[6]  * v2 + MT[7]  * v3;
            v[dc*4+2] = MT[9]  * v1 + MT[10] * v2 + MT[11] * v3;
            v[dc*4+3] = MT[12] * v0 + MT[13] * v1 + MT[14] * v2 + MT[15] * v3;
        }
    }
    if (HASMC) {
#pragma unroll
        for (int dt = 0; dt < 4; dt++) {
            float v0 = v[0+dt], v1 = v[4+dt], v2 = v[8+dt], v3 = v[12+dt];
            v[4 + dt]  = MC[5]  * v1 + MC[6]  * v2 + MC[7]  * v3;
            v[8 + dt]  = MC[9]  * v1 + MC[10] * v2 + MC[11] * v3;
            v[12 + dt] = MC[12] * v0 + MC[13] * v1 + MC[14] * v2 + MC[15] * v3;
        }
    }

    const int tbl[16] = {0, 1, 14, 15, 5, 4, 11, 10, 9, 8, 7, 6, 12, 13, 2, 3};
    float w_[16];
#pragma unroll
    for (int i = 0; i < 16; i++) w_[i] = v[tbl[i]];
    w_[7]  = -w_[7];
    w_[10] = -w_[10];
#pragma unroll
    for (int dt = 0; dt < 4; dt++) {
        float u0 = w_[0+dt], u1 = w_[4+dt], u2 = w_[8+dt], u3 = w_[12+dt];
        w_[4 + dt]  = aN * u1;
        w_[8 + dt]  = aN * u2;
        w_[12 + dt] = gN * u0 + zN * u3;
    }
#pragma unroll
    for (int dc = 0; dc < 4; dc++) {
        float u0 = w_[dc*4+0], u1 = w_[dc*4+1], u2 = w_[dc*4+2], u3 = w_[dc*4+3];
        w_[dc*4+1] = aN * u1;
        w_[dc*4+2] = aN * u2;
        w_[dc*4+3] = gN * u0 + zN * u3;
    }
#pragma unroll
    for (int dc = 0; dc < 4; dc++)
#pragma unroll
        for (int dt = 0; dt < 4; dt++) {
            unsigned off = ((unsigned)dc << sc) | ((unsigned)dt << st);
            t[pb ^ off ^ SWf(off)] = w_[dc * 4 + dt];
        }
}

template<int KIND>
__device__ __forceinline__ unsigned gidx(unsigned u, unsigned tile) {
    if (KIND == 0) return u | (tile << 12);
    else           return (u & 15u) | (tile << 4) | ((u >> 4) << 12);
}

// One tile through a stage (R4 body, 256 threads).
// MASKLOAD (KIND 1 only): load only elements whose bits12-19 digits are I/Z.
template<int KIND, bool INIT, bool PRUNE, bool STORE, bool MASKLOAD>
__device__ __forceinline__ void stage_body(const float* __restrict__ wts,
                                           int layer, unsigned blk,
                                           float* t, float sM[10][16]) {
    unsigned tid = threadIdx.x;
    if (INIT) {
        for (unsigned u = tid; u < 4096; u += 256) {
            unsigned p = gidx<KIND>(u, blk);
            t[u ^ SWf(u)] = ((((p >> 1) ^ p) & 0x55555u) == 0u) ? 1.0f : 0.0f;
        }
    } else {
#pragma unroll
        for (int i = 0; i < 4; i++) {
            unsigned u = (tid + i * 256u) * 4u;
            float4 r;
            if (MASKLOAD) {
                unsigned d = (u >> 4) & 0xFFu;   // constant across the float4
                if ((((d >> 1) ^ d) & 0x55u) == 0u)
                    r = *(const float4*)&g_c[gidx<KIND>(u, blk)];
                else
                    r = make_float4(0.f, 0.f, 0.f, 0.f);
            } else {
                r = *(const float4*)&g_c[gidx<KIND>(u, blk)];
            }
            unsigned sw = SWf(u);
            t[(u + 0) ^ sw] = r.x;
            t[(u + 1) ^ sw] = r.y;
            t[(u + 2) ^ sw] = r.z;
            t[(u + 3) ^ sw] = r.w;
        }
    }
    if (tid < 10) {
        const float* a = wts + (layer * 10 + (int)tid) * 3;
        build_M(a[0], a[1], a[2], sM[tid]);
    }
    __syncthreads();

    const float gamma = -expm1f(-1e-7f / 0.05f);
    const float gph   = -expm1f(-1e-7f / 0.07f);
    const float c2    = 1.0f - 4.0f * 0.01f / 3.0f;
    const float aN = sqrtf((1.f - gamma) * (1.f - gph)) * c2;
    const float zN = (1.f - gamma) * c2;
    const float gN = gamma;

    if (KIND == 0) {
        pass<0, 2, true, true >(t, sM[1], sM[0], aN, zN, gN); __syncthreads();
        pass<2, 3, true, false>(t, sM[2], 0,     aN, zN, gN); __syncthreads();
        pass<3, 4, true, false>(t, sM[3], 0,     aN, zN, gN); __syncthreads();
        pass<4, 5, true, false>(t, sM[4], 0,     aN, zN, gN); __syncthreads();
        pass<5, 1, true, false>(t, sM[5], 0,     aN, zN, gN); __syncthreads();
    } else {
        pass<1, 2, true, false>(t, sM[6], 0, aN, zN, gN); __syncthreads();
        pass<2, 3, true, false>(t, sM[7], 0, aN, zN, gN); __syncthreads();
        pass<3, 4, true, false>(t, sM[8], 0, aN, zN, gN); __syncthreads();
        pass<4, 5, true, false>(t, sM[9], 0, aN, zN, gN); __syncthreads();
        pass<5, 0, false,false>(t, 0,     0, aN, zN, gN); __syncthreads();
    }

    if (STORE) {
#pragma unroll
        for (int i = 0; i < 4; i++) {
            unsigned u = (tid + i * 256u) * 4u;
            if (PRUNE) {
                unsigned vsel = (u >> 4) & 0xFFu;
                if (!((PRMASK[vsel >> 6] >> (vsel & 63u)) & 1ull)) continue;
            }
            unsigned sw = SWf(u);
            float4 r;
            r.x = t[(u + 0) ^ sw];
            r.y = t[(u + 1) ^ sw];
            r.z = t[(u + 2) ^ sw];
            r.w = t[(u + 3) ^ sw];
            *(float4*)&g_c[gidx<KIND>(u, blk)] = r;
        }
    }
}

// ---------------------------------------------------------------------------
// feats: warp-per-row, register-resident, no smem/syncs (R12-verified).
// ---------------------------------------------------------------------------
__device__ __forceinline__ float dot4(const float* a, const float* b) {
    return a[0]*b[0] + a[1]*b[1] + a[2]*b[2] + a[3]*b[3];
}

__device__ void feats_body(const float* __restrict__ x,
                           const float* __restrict__ bvec, int fblk) {
    int lane = threadIdx.x & 31;
    int row  = fblk * 8 + (threadIdx.x >> 5);
    const float4* xr = (const float4*)(x + row * 1024);
    const float4* br = (const float4*)bvec;

    float e[8][4];
#pragma unroll
    for (int t = 0; t < 8; t++) {
        float4 xv = xr[lane + 32 * t];
        float4 bb = br[lane + 32 * t];
        e[t][0] = xv.x + bb.x; e[t][1] = xv.y + bb.y;
        e[t][2] = xv.z + bb.z; e[t][3] = xv.w + bb.w;
    }

    float fA[10], fZ[10];
#pragma unroll
    for (int j = 0; j < 10; j++) { fA[j] = 0.f; fZ[j] = 0.f; }
    float Stot = 0.f;

#pragma unroll
    for (int t = 0; t < 8; t++) {
        float s0 = e[t][0]*e[t][0], s1 = e[t][1]*e[t][1];
        float s2 = e[t][2]*e[t][2], s3 = e[t][3]*e[t][3];
        float St = (s0 + s1) + (s2 + s3);
        Stot += St;
        fZ[0] += (s0 - s1) + (s2 - s3);
        fZ[1] += (s0 + s1) - (s2 + s3);
        fZ[7] += (t & 1) ? -St : St;
        fZ[8] += (t & 2) ? -St : St;
        fZ[9] += (t & 4) ? -St : St;
        fA[0] += 2.f * (e[t][0]*e[t][1] + e[t][2]*e[t][3]);
        fA[1] += 2.f * (e[t][0]*e[t][2] + e[t][1]*e[t][3]);
    }
#pragma unroll
    for (int j = 2; j <= 6; j++)
        fZ[j] = ((lane >> (j - 2)) & 1) ? -Stot : Stot;

    fA[7] = 2.f * (dot4(e[0],e[1]) + dot4(e[2],e[3]) + dot4(e[4],e[5]) + dot4(e[6],e[7]));
    fA[8] = 2.f * (dot4(e[0],e[2]) + dot4(e[1],e[3]) + dot4(e[4],e[6]) + dot4(e[5],e[7]));
    fA[9] = 2.f * (dot4(e[0],e[4]) + dot4(e[1],e[5]) + dot4(e[2],e[6]) + dot4(e[3],e[7]));

#pragma unroll
    for (int j = 2; j <= 6; j++) {
        int b = 1 << (j - 2);
        float acc = 0.f;
#pragma unroll
        for (int t = 0; t < 8; t++)
#pragma unroll
            for (int k = 0; k < 4; k++) {
                float nb = __shfl_xor_sync(0xFFFFFFFFu, e[t][k], b);
                acc += e[t][k] * nb;
            }
        fA[j] = acc;
    }

#pragma unroll
    for (int j = 0; j < 10; j++) {
#pragma unroll
        for (int off = 16; off > 0; off >>= 1) {
            fA[j] += __shfl_down_sync(0xFFFFFFFFu, fA[j], off);
            fZ[j] += __shfl_down_sync(0xFFFFFFFFu, fZ[j], off);
        }
    }
    if (lane == 0) {
#pragma unroll
        for (int j = 0; j < 10; j++) {
            g_feats[row * 20 + j]      = fA[j];
            g_feats[row * 20 + 10 + j] = fZ[j];
        }
    }
}

// ---------------------------------------------------------------------------
// K1: blocks 0-15 = sim stage A0 (only the 16 nonzero tiles: slots 6-9 digits
// all in {I,Z}); blocks 16-271 = feats (8 rows each).
// ---------------------------------------------------------------------------
__global__ __launch_bounds__(256) void k1_kernel(const float* __restrict__ wts,
                                                 const float* __restrict__ x,
                                                 const float* __restrict__ bvec) {
    __shared__ float t[4096];
    __shared__ float sM[10][16];
    if (blockIdx.x < 16) {
        unsigned b = blockIdx.x;
        unsigned tile = 0;
        if (b & 1) tile |= 3u;
        if (b & 2) tile |= 3u << 2;
        if (b & 4) tile |= 3u << 4;
        if (b & 8) tile |= 3u << 6;
        stage_body<0, true, false, true, false>(wts, 0, tile, t, sM);
    } else {
        feats_body(x, bvec, (int)blockIdx.x - 16);
    }
}

// Generic sim stage kernel. REMAP: 9 observable tiles; emits g_we, no stores.
template<int KIND, bool PRUNE, bool REMAP, bool MASKLOAD>
__global__ __launch_bounds__(256) void sim_kernel(const float* __restrict__ wts,
                                                  const float* __restrict__ w,
                                                  int layer) {
    __shared__ float t[4096];
    __shared__ float sM[10][16];
    unsigned blk = REMAP ? (unsigned)TILE9[blockIdx.x] : blockIdx.x;
    stage_body<KIND, false, PRUNE, !REMAP, MASKLOAD>(wts, layer, blk, t, sM);
    if (REMAP) {
        unsigned tid = threadIdx.x;
        if (tid < 20 && (unsigned)OBS_T[tid] == blk) {
            unsigned u = (unsigned)OBS_U[tid];
            float v = t[u ^ SWf(u)];
            float coef = w[(int)OBS_W[tid]] * (tid < 10 ? 1.0f : 0.96f);
            g_we[tid] = coef * v;
        }
    }
}

// Final: logit[row] = dot(feats[row], we); sigmoid.
__global__ __launch_bounds__(256) void final_kernel(float* __restrict__ out) {
    int row = blockIdx.x * 256 + threadIdx.x;
    const float4* f = (const float4*)(g_feats + row * 20);
    float acc = 0.f;
#pragma unroll
    for (int i = 0; i < 5; i++) {
        float4 v = f[i];
        acc += v.x * g_we[i*4+0] + v.y * g_we[i*4+1]
             + v.z * g_we[i*4+2] + v.w * g_we[i*4+3];
    }
    out[row] = 1.f / (1.f + expf(-acc));
}

// ---------------------------------------------------------------------------
extern "C" void kernel_launch(void* const* d_in, const int* in_sizes, int n_in,
                              void* d_out, int out_size) {
    const float* x = nullptr;
    const float* bv = nullptr;
    const float* w = nullptr;
    const float* cw = nullptr;
    for (int i = 0; i < n_in; i++) {
        switch (in_sizes[i]) {
            case 2048 * 1024: x = (const float*)d_in[i]; break;
            case 1024:        bv = (const float*)d_in[i]; break;
            case 20:          w = (const float*)d_in[i]; break;
            case 90:          cw = (const float*)d_in[i]; break;
            default: break;  // P_tensor unused
        }
    }

    // Template args: <KIND, PRUNE, REMAP, MASKLOAD>
    k1_kernel<<<272, 256>>>(cw, x, bv);                               // A0(16) + feats
    sim_kernel<1, false, false, true ><<<256, 256>>>(cw, w, 0);       // B0 (masked load)
    sim_kernel<0, false, false, false><<<256, 256>>>(cw, w, 1);       // A1
    sim_kernel<1, false, false, false><<<256, 256>>>(cw, w, 1);       // B1
    sim_kernel<0, true,  false, false><<<256, 256>>>(cw, w, 2);       // A2 (PRUNE)
    sim_kernel<1, false, true,  false><<<9,   256>>>(cw, w, 2);       // B2 (REMAP) -> g_we
    final_kernel<<<8, 256>>>((float*)d_out);                          // dot + sigmoid
}